// round 2
// baseline (speedup 1.0000x reference)
#include <cuda_runtime.h>
#include <cuda_bf16.h>

// RetinaFaceDecoder: N=1e6 rows of 16 floats (4 loc, 2 cls, 10 landm) + priors [N,4].
// Output (flattened tuple, fp32):
//   [0      , 4N )  boxes_m   (tl.x tl.y br.x br.y) * m
//   [4N     , 5N )  conf_m
//   [5N     , 6N )  pred_m    (always 0: only class 1 passes, pred-1 == 0)
//   [6N     , 22N)  detections [boxes(4), conf, pred, landms(10)] per row
//   [22N    , 23N)  keep      (0/1)
//
// Pure streaming kernel: no reuse -> .cs load/store hints, float4 vectorization.

__global__ __launch_bounds__(256) void retinaface_decode_kernel(
    const float4* __restrict__ in,      // 4 x float4 per row
    const float4* __restrict__ priors,  // 1 x float4 per row
    const float*  __restrict__ thr_p,   // 1
    const float*  __restrict__ var_p,   // 2
    float* __restrict__ out,
    int N)
{
    int i = blockIdx.x * blockDim.x + threadIdx.x;
    if (i >= N) return;

    // broadcast scalars (L2-cached, negligible)
    const float v0  = var_p[0];
    const float v1  = var_p[1];
    const float thr = thr_p[0];

    // row loads (streaming: no reuse)
    float4 r0 = __ldcs(in + 4ll * i + 0);  // loc: cx cy w h
    float4 r1 = __ldcs(in + 4ll * i + 1);  // c0 c1 lm0x lm0y
    float4 r2 = __ldcs(in + 4ll * i + 2);  // lm1x lm1y lm2x lm2y
    float4 r3 = __ldcs(in + 4ll * i + 3);  // lm3x lm3y lm4x lm4y
    float4 p  = __ldcs(priors + i);        // px py pw ph

    // 2-class softmax max-prob + argmax
    float d    = r1.y - r1.x;                       // c1 - c0
    float conf = 1.0f / (1.0f + expf(-fabsf(d)));   // max softmax prob
    bool  keep = (d > 0.0f) && (conf > thr);        // argmax==1 (tie -> class 0) & threshold
    float m    = keep ? 1.0f : 0.0f;

    // decode box
    float cx = fmaf(r0.x * v0, p.z, p.x);
    float cy = fmaf(r0.y * v0, p.w, p.y);
    float w  = p.z * expf(r0.z * v1);
    float h  = p.w * expf(r0.w * v1);
    float tlx = cx - 0.5f * w;
    float tly = cy - 0.5f * h;
    float brx = tlx + w;
    float bry = tly + h;

    float4 box = make_float4(tlx * m, tly * m, brx * m, bry * m);

    // decode 5 landmarks: pt = prior.xy + lm * v0 * prior.wh, masked
    float sx = v0 * p.z, sy = v0 * p.w;
    float l0x = fmaf(r1.z, sx, p.x) * m, l0y = fmaf(r1.w, sy, p.y) * m;
    float l1x = fmaf(r2.x, sx, p.x) * m, l1y = fmaf(r2.y, sy, p.y) * m;
    float l2x = fmaf(r2.z, sx, p.x) * m, l2y = fmaf(r2.w, sy, p.y) * m;
    float l3x = fmaf(r3.x, sx, p.x) * m, l3y = fmaf(r3.y, sy, p.y) * m;
    float l4x = fmaf(r3.z, sx, p.x) * m, l4y = fmaf(r3.w, sy, p.y) * m;

    float confm = conf * m;

    long long Nl = N;

    // boxes_m: contiguous float4 per thread
    __stcs(reinterpret_cast<float4*>(out) + i, box);
    // conf_m
    __stcs(out + 4 * Nl + i, confm);
    // pred_m: identically zero (pred-1 == 0 whenever keep)
    __stcs(out + 5 * Nl + i, 0.0f);
    // detections [1,N,16]
    float4* det = reinterpret_cast<float4*>(out + 6 * Nl + 16ll * i);
    __stcs(det + 0, box);
    __stcs(det + 1, make_float4(confm, 0.0f, l0x, l0y));
    __stcs(det + 2, make_float4(l1x, l1y, l2x, l2y));
    __stcs(det + 3, make_float4(l3x, l3y, l4x, l4y));
    // keep
    __stcs(out + 22 * Nl + i, m);
}

extern "C" void kernel_launch(void* const* d_in, const int* in_sizes, int n_in,
                              void* d_out, int out_size)
{
    // Inputs in metadata order: input [1,N,16], score_threshold [1], priors [N,4], variance [2].
    // Identify defensively by size so ordering quirks can't break us.
    const float* input  = nullptr;
    const float* thr    = nullptr;
    const float* priors = nullptr;
    const float* var    = nullptr;
    long long input_sz = 0, priors_sz = 0;

    for (int k = 0; k < n_in; k++) {
        long long sz = in_sizes[k];
        const float* p = (const float*)d_in[k];
        if (sz == 1)            thr = p;
        else if (sz == 2)       var = p;
        else if (sz > input_sz) { // largest = input; runner-up = priors
            if (input) { priors = input; priors_sz = input_sz; }
            input = p; input_sz = sz;
        } else if (sz > priors_sz) {
            priors = p; priors_sz = sz;
        }
    }

    int N = (int)(input_sz / 16);

    int threads = 256;
    int blocks  = (N + threads - 1) / threads;
    retinaface_decode_kernel<<<blocks, threads>>>(
        (const float4*)input, (const float4*)priors, thr, var,
        (float*)d_out, N);
}

// round 3
// speedup vs baseline: 1.0146x; 1.0146x over previous
#include <cuda_runtime.h>
#include <cuda_bf16.h>

// RetinaFaceDecoder, smem-staged fully-coalesced version.
// Output layout (fp32): [boxes 4N | conf N | pred N (=0) | det 16N | keep N]
//
// Round-2 ncu showed L1=61.6% > DRAM=49.2%: the per-row strided LDG/STG pattern
// inflated L1 wavefronts ~4x. This version stages the 16-float rows through
// shared memory (pad 17 to avoid bank conflicts) so all gmem traffic is linear.

#define ROWS 256
#define PAD  17

__global__ __launch_bounds__(ROWS) void retinaface_decode_kernel(
    const float4* __restrict__ in,      // [N*4] float4 (16 floats/row)
    const float4* __restrict__ priors,  // [N] float4
    const float*  __restrict__ thr_p,   // 1
    const float*  __restrict__ var_p,   // 2
    float* __restrict__ out,
    int N)
{
    __shared__ float s[ROWS * PAD];   // 17408 B, reused for input rows then det rows

    const int t    = threadIdx.x;
    const int base = blockIdx.x * ROWS;
    const int rows = min(ROWS, N - base);

    // ---- Phase 1: coalesced gmem -> smem staging of input rows ----
    {
        const float4* in4 = in + 4ll * base;
        #pragma unroll
        for (int n = 0; n < 4; n++) {
            int k4 = t + n * ROWS;            // 0..1023 float4 slots for this block
            if (k4 < rows * 4) {
                float4 v = __ldcs(in4 + k4);
                int row = k4 >> 2;
                int c   = (k4 & 3) << 2;
                float* dst = &s[row * PAD + c];
                dst[0] = v.x; dst[1] = v.y; dst[2] = v.z; dst[3] = v.w;
            }
        }
    }
    __syncthreads();

    // ---- Phase 2: per-thread compute from smem (stride-17 -> conflict-free) ----
    const float v0  = var_p[0];
    const float v1  = var_p[1];
    const float thr = thr_p[0];

    float det0, det1, det2, det3;          // box
    float detc;                            // conf
    float l0x,l0y,l1x,l1y,l2x,l2y,l3x,l3y,l4x,l4y;
    float m = 0.0f;
    const bool valid = (t < rows);
    const long long Nl = N;
    const long long i  = base + t;

    if (valid) {
        const float* r = &s[t * PAD];
        float c0 = r[4], c1 = r[5];
        float4 p = __ldcs(priors + i);     // contiguous float4/thread: coalesced

        float d    = c1 - c0;
        float conf = 1.0f / (1.0f + expf(-fabsf(d)));
        bool  keep = (d > 0.0f) && (conf > thr);
        m = keep ? 1.0f : 0.0f;

        float cx = fmaf(r[0] * v0, p.z, p.x);
        float cy = fmaf(r[1] * v0, p.w, p.y);
        float w  = p.z * expf(r[2] * v1);
        float h  = p.w * expf(r[3] * v1);
        float tlx = cx - 0.5f * w;
        float tly = cy - 0.5f * h;

        det0 = tlx * m;
        det1 = tly * m;
        det2 = (tlx + w) * m;
        det3 = (tly + h) * m;
        detc = conf * m;

        float sx = v0 * p.z, sy = v0 * p.w;
        l0x = fmaf(r[ 6], sx, p.x) * m;  l0y = fmaf(r[ 7], sy, p.y) * m;
        l1x = fmaf(r[ 8], sx, p.x) * m;  l1y = fmaf(r[ 9], sy, p.y) * m;
        l2x = fmaf(r[10], sx, p.x) * m;  l2y = fmaf(r[11], sy, p.y) * m;
        l3x = fmaf(r[12], sx, p.x) * m;  l3y = fmaf(r[13], sy, p.y) * m;
        l4x = fmaf(r[14], sx, p.x) * m;  l4y = fmaf(r[15], sy, p.y) * m;

        // Already-coalesced small outputs
        __stcs(reinterpret_cast<float4*>(out) + i, make_float4(det0, det1, det2, det3));
        __stcs(out +  4 * Nl + i, detc);
        __stcs(out +  5 * Nl + i, 0.0f);   // pred-1 == 0 whenever kept
        __stcs(out + 22 * Nl + i, m);
    }
    __syncthreads();   // everyone done reading s before det overwrite

    // ---- Phase 3: det rows -> smem (stride-17 writes: conflict-free) ----
    if (valid) {
        float* q = &s[t * PAD];
        q[ 0] = det0; q[ 1] = det1; q[ 2] = det2; q[ 3] = det3;
        q[ 4] = detc; q[ 5] = 0.0f;
        q[ 6] = l0x;  q[ 7] = l0y;
        q[ 8] = l1x;  q[ 9] = l1y;
        q[10] = l2x;  q[11] = l2y;
        q[12] = l3x;  q[13] = l3y;
        q[14] = l4x;  q[15] = l4y;
    }
    __syncthreads();

    // ---- Phase 4: coalesced smem -> gmem det store ----
    {
        float4* det4 = reinterpret_cast<float4*>(out + 6 * Nl) + 4ll * base;
        #pragma unroll
        for (int n = 0; n < 4; n++) {
            int k4 = t + n * ROWS;
            if (k4 < rows * 4) {
                int row = k4 >> 2;
                int c   = (k4 & 3) << 2;
                const float* src = &s[row * PAD + c];
                __stcs(det4 + k4, make_float4(src[0], src[1], src[2], src[3]));
            }
        }
    }
}

extern "C" void kernel_launch(void* const* d_in, const int* in_sizes, int n_in,
                              void* d_out, int out_size)
{
    // Inputs: input [1,N,16], score_threshold [1], priors [N,4], variance [2].
    const float* input  = nullptr;
    const float* thr    = nullptr;
    const float* priors = nullptr;
    const float* var    = nullptr;
    long long input_sz = 0, priors_sz = 0;

    for (int k = 0; k < n_in; k++) {
        long long sz = in_sizes[k];
        const float* p = (const float*)d_in[k];
        if (sz == 1)            thr = p;
        else if (sz == 2)       var = p;
        else if (sz > input_sz) {
            if (input) { priors = input; priors_sz = input_sz; }
            input = p; input_sz = sz;
        } else if (sz > priors_sz) {
            priors = p; priors_sz = sz;
        }
    }

    int N = (int)(input_sz / 16);

    int blocks = (N + ROWS - 1) / ROWS;
    retinaface_decode_kernel<<<blocks, ROWS>>>(
        (const float4*)input, (const float4*)priors, thr, var,
        (float*)d_out, N);
}